// round 7
// baseline (speedup 1.0000x reference)
#include <cuda_runtime.h>
#include <cuda_fp16.h>
#include <cstdint>

// Bilinear attention, B=16, T=D=1024:
//   qW = query @ W ; logits = qW @ keys^T + mask ; score = softmax(logits) ; ctx = score @ values
// GEMMs via mma.sync.m16n8k16 fp16, error-compensated split, fp32 accumulate.
// Producer-side split into half2 planes (A-hi/A-lo/B-hi/B-lo); fragments loaded
// with ldmatrix.x4 (conflict-free 80B row stride). K-chunk 32 (2 k16 subchunks
// per CTA barrier), 2-slot ring. All GEMMs NT. 128 thr/CTA, warp tile 64x64.

#define NDIM 1024

// Static scratch (allocation-guard safe)
__device__ float g_qW[16777216];    // 16384 x 1024
__device__ float g_Wt[1048576];     // W^T
__device__ float g_valT[16777216];  // values^T per batch

// ---- helpers -------------------------------------------------------------
static __device__ __forceinline__ uint32_t smem_u32(const void* p) {
    uint32_t a;
    asm("{ .reg .u64 t; cvta.to.shared.u64 t, %1; cvt.u32.u64 %0, t; }" : "=r"(a) : "l"(p));
    return a;
}
static __device__ __forceinline__ uint32_t pack_h2(float e0, float e1) {
    uint32_t r;   // r.lo = f16(e0), r.hi = f16(e1)
    asm("cvt.rn.f16x2.f32 %0, %1, %2;" : "=r"(r) : "f"(e1), "f"(e0));
    return r;
}
static __device__ __forceinline__ void split_pair(float x, float y, uint32_t& h, uint32_t& l) {
    h = pack_h2(x, y);
    __half2 hh = *reinterpret_cast<__half2*>(&h);
    l = pack_h2(x - __low2float(hh), y - __high2float(hh));
}
static __device__ __forceinline__ void mma16(float* d, const uint32_t* a, const uint32_t* b) {
    asm volatile(
        "mma.sync.aligned.m16n8k16.row.col.f32.f16.f16.f32 "
        "{%0,%1,%2,%3}, {%4,%5,%6,%7}, {%8,%9}, {%0,%1,%2,%3};"
        : "+f"(d[0]), "+f"(d[1]), "+f"(d[2]), "+f"(d[3])
        : "r"(a[0]), "r"(a[1]), "r"(a[2]), "r"(a[3]), "r"(b[0]), "r"(b[1]));
}
static __device__ __forceinline__ void ldsm4(uint32_t* r, uint32_t addr) {
    asm volatile("ldmatrix.sync.aligned.m8n8.x4.shared.b16 {%0,%1,%2,%3}, [%4];"
        : "=r"(r[0]), "=r"(r[1]), "=r"(r[2]), "=r"(r[3]) : "r"(addr));
}

// ---- SMEM plane layout ----------------------------------------------------
// Row = 32 halves data (64B) + 16B pad = 80B. Planes: A-hi/A-lo/B-hi/B-lo,
// 128 rows x 80B = 10240 B each. 2 slots.
#define ROWB 80
#define PLANE 10240
#define AH_OFF 0
#define AL_OFF PLANE
#define BH_OFF (2 * PLANE)
#define BL_OFF (3 * PLANE)
#define SLOT_BYTES (4 * PLANE)
static constexpr int SMEM_BYTES = 2 * SLOT_BYTES;   // 81920

// TERMS==3: Ahi*Bhi + Ahi*Blo + Alo*Bhi (near-fp32; logit path)
// TERMS==2: Ahi*Bhi + Alo*Bhi            (full-A x f16-B; post-softmax GEMM)
template<bool ADDMASK, int TERMS>
__global__ __launch_bounds__(128) void gemm_fp16_kernel(
    const float* __restrict__ A, const float* __restrict__ B,
    float* __restrict__ C, const float* __restrict__ mask,
    size_t sA, size_t sB, size_t sC)
{
    extern __shared__ __align__(16) char smem[];
    const uint32_t su = smem_u32(smem);
    const int tid = threadIdx.x, wid = tid >> 5, lid = tid & 31;
    const int g = lid >> 2, tg = lid & 3;                  // mma group / thread-in-group
    const int wm = (wid >> 1) * 64, wn = (wid & 1) * 64;   // 2x2 warp grid, 64x64 tiles
    const int M0 = blockIdx.y * 128, N0 = blockIdx.x * 128;
    const size_t b = blockIdx.z;
    A += b * sA; B += b * sB; C += b * sC;
    const float* mp = ADDMASK ? (mask + b * 1024) : nullptr;

    // ldmatrix per-thread row/koff geometry
    const int lrow = lid & 15;                 // A: row within m16 group
    const int lk   = (lid >> 4) * 16;          // A: 0 or +16B (k 0-7 / 8-15)
    const int brow = ((lid >> 4) << 3) + (lid & 7);   // B: row within 16-n pair
    const int bk   = ((lid >> 3) & 1) * 16;           // B: 0 or +16B

    // producer geometry: r = row (0..31, +32/pass), q = k-quarter within k16
    const int r = tid >> 2, q = tid & 3;
    const float* Ag = A + (size_t)(M0 + r) * NDIM + 4 * q;
    const float* Bg = B + (size_t)(N0 + r) * NDIM + 4 * q;

    float acc[4][8][4];
    #pragma unroll
    for (int mi = 0; mi < 4; mi++)
        #pragma unroll
        for (int ni = 0; ni < 8; ni++)
            #pragma unroll
            for (int v = 0; v < 4; v++) acc[mi][ni][v] = 0.0f;

    float4 bufA[4], bufB[4];

    // load k16 half h of chunk c (chunk = 32 k)
    auto ldg_half = [&](int c, int h) {
        const int k0 = (c << 5) + (h << 4);
        #pragma unroll
        for (int p = 0; p < 4; p++) {
            bufA[p] = *(const float4*)(Ag + (size_t)32 * p * NDIM + k0);
            bufB[p] = *(const float4*)(Bg + (size_t)32 * p * NDIM + k0);
        }
    };

    auto sts_half = [&](int slot, int h) {
        char* base = smem + slot * SLOT_BYTES;
        #pragma unroll
        for (int p = 0; p < 4; p++) {
            const int ro = (r + 32 * p) * ROWB + h * 32 + q * 8;
            uint32_t h0, h1, l0, l1;
            split_pair(bufA[p].x, bufA[p].y, h0, l0);
            split_pair(bufA[p].z, bufA[p].w, h1, l1);
            *(uint2*)(base + AH_OFF + ro) = make_uint2(h0, h1);
            *(uint2*)(base + AL_OFF + ro) = make_uint2(l0, l1);
            if (TERMS == 3) {
                split_pair(bufB[p].x, bufB[p].y, h0, l0);
                split_pair(bufB[p].z, bufB[p].w, h1, l1);
                *(uint2*)(base + BH_OFF + ro) = make_uint2(h0, h1);
                *(uint2*)(base + BL_OFF + ro) = make_uint2(l0, l1);
            } else {
                h0 = pack_h2(bufB[p].x, bufB[p].y);
                h1 = pack_h2(bufB[p].z, bufB[p].w);
                *(uint2*)(base + BH_OFF + ro) = make_uint2(h0, h1);
            }
        }
    };

    // one k16 subchunk of MMAs from slot, subchunk h
    auto mma_sub = [&](int slot, int h) {
        const uint32_t base = su + slot * SLOT_BYTES;
        const int koff = h * 32;
        uint32_t bh[8][2], bl[8][2];
        #pragma unroll
        for (int j = 0; j < 4; j++) {           // ni pair j -> ni 2j, 2j+1
            uint32_t t4[4];
            const uint32_t ba = base + BH_OFF + (wn + 16 * j + brow) * ROWB + koff + bk;
            ldsm4(t4, ba);
            bh[2*j][0] = t4[0]; bh[2*j][1] = t4[1];
            bh[2*j+1][0] = t4[2]; bh[2*j+1][1] = t4[3];
            if (TERMS == 3) {
                ldsm4(t4, ba + (BL_OFF - BH_OFF));
                bl[2*j][0] = t4[0]; bl[2*j][1] = t4[1];
                bl[2*j+1][0] = t4[2]; bl[2*j+1][1] = t4[3];
            }
        }
        #pragma unroll
        for (int mi = 0; mi < 4; mi++) {
            uint32_t ah[4], al[4];
            const uint32_t aa = base + AH_OFF + (wm + mi * 16 + lrow) * ROWB + koff + lk;
            ldsm4(ah, aa);
            ldsm4(al, aa + (AL_OFF - AH_OFF));
            #pragma unroll
            for (int ni = 0; ni < 8; ni++) {
                mma16(acc[mi][ni], ah, bh[ni]);
                if (TERMS == 3) mma16(acc[mi][ni], ah, bl[ni]);
                mma16(acc[mi][ni], al, bh[ni]);
            }
        }
    };

    // prologue: fill slot 0 (chunk 0)
    ldg_half(0, 0);
    sts_half(0, 0);
    ldg_half(0, 1);
    sts_half(0, 1);
    __syncthreads();

    for (int c = 0; c < 32; c++) {
        const int slot = c & 1, nslot = (c + 1) & 1;
        const bool more = (c + 1 < 32);
        if (more) ldg_half(c + 1, 0);
        mma_sub(slot, 0);
        if (more) { sts_half(nslot, 0); ldg_half(c + 1, 1); }
        mma_sub(slot, 1);
        if (more) sts_half(nslot, 1);
        __syncthreads();
    }

    // epilogue: d0,d1 at (g, 2tg..2tg+1), d2,d3 at (g+8, ...)
    #pragma unroll
    for (int mi = 0; mi < 4; mi++) {
        #pragma unroll
        for (int ni = 0; ni < 8; ni++) {
            const int r0 = M0 + wm + mi * 16 + g;
            const int cc = N0 + wn + ni * 8 + 2 * tg;
            float2 v0 = make_float2(acc[mi][ni][0], acc[mi][ni][1]);
            float2 v1 = make_float2(acc[mi][ni][2], acc[mi][ni][3]);
            if (ADDMASK) {
                const float m0v = mp[cc], m1v = mp[cc + 1];
                v0.x += m0v; v0.y += m1v;
                v1.x += m0v; v1.y += m1v;
            }
            *(float2*)(C + (size_t)r0 * NDIM + cc)       = v0;
            *(float2*)(C + (size_t)(r0 + 8) * NDIM + cc) = v1;
        }
    }
}

// 1024x1024 f32 transpose (per blockIdx.z slice), block (32,8)
__global__ __launch_bounds__(256) void transpose_kernel(const float* __restrict__ src,
                                                        float* __restrict__ dst)
{
    __shared__ float t[32][33];
    const size_t b = blockIdx.z;
    src += b * 1048576ull; dst += b * 1048576ull;
    const int bx = blockIdx.x * 32, by = blockIdx.y * 32;
    const int x = threadIdx.x, y4 = threadIdx.y * 4;
    #pragma unroll
    for (int i = 0; i < 4; i++)
        t[y4 + i][x] = src[(size_t)(by + y4 + i) * 1024 + bx + x];
    __syncthreads();
    #pragma unroll
    for (int i = 0; i < 4; i++)
        dst[(size_t)(bx + y4 + i) * 1024 + by + x] = t[x][y4 + i];
}

// In-place row softmax, row length 1024
__global__ __launch_bounds__(256) void softmax_kernel(float* __restrict__ S)
{
    __shared__ float red[8];
    size_t row = blockIdx.x;
    float4* p = reinterpret_cast<float4*>(S + row * 1024);
    int t = threadIdx.x;

    float4 v = p[t];
    float m = fmaxf(fmaxf(v.x, v.y), fmaxf(v.z, v.w));
    #pragma unroll
    for (int o = 16; o; o >>= 1) m = fmaxf(m, __shfl_xor_sync(0xffffffffu, m, o));
    if ((t & 31) == 0) red[t >> 5] = m;
    __syncthreads();
    m = red[0];
    #pragma unroll
    for (int i = 1; i < 8; i++) m = fmaxf(m, red[i]);

    v.x = expf(v.x - m); v.y = expf(v.y - m);
    v.z = expf(v.z - m); v.w = expf(v.w - m);
    float s = v.x + v.y + v.z + v.w;
    #pragma unroll
    for (int o = 16; o; o >>= 1) s += __shfl_xor_sync(0xffffffffu, s, o);
    __syncthreads();
    if ((t & 31) == 0) red[t >> 5] = s;
    __syncthreads();
    s = red[0];
    #pragma unroll
    for (int i = 1; i < 8; i++) s += red[i];

    float inv = 1.0f / s;
    v.x *= inv; v.y *= inv; v.z *= inv; v.w *= inv;
    p[t] = v;
}

extern "C" void kernel_launch(void* const* d_in, const int* in_sizes, int n_in,
                              void* d_out, int out_size)
{
    (void)in_sizes; (void)n_in; (void)out_size;
    const float* query  = (const float*)d_in[0];   // [16,1024,1024]
    const float* keys   = (const float*)d_in[1];   // [16,1024,1024]
    const float* values = (const float*)d_in[2];   // [16,1024,1024]
    const float* W      = (const float*)d_in[3];   // [1024,1024]
    const float* mask   = (const float*)d_in[4];   // [16,1024]

    float* score = (float*)d_out;                        // [16,1024,1024]
    float* ctx   = score + (size_t)16 * 1024 * 1024;     // [16,1024,1024]

    cudaFuncSetAttribute(gemm_fp16_kernel<false, 3>,
                         cudaFuncAttributeMaxDynamicSharedMemorySize, SMEM_BYTES);
    cudaFuncSetAttribute(gemm_fp16_kernel<true, 3>,
                         cudaFuncAttributeMaxDynamicSharedMemorySize, SMEM_BYTES);
    cudaFuncSetAttribute(gemm_fp16_kernel<false, 2>,
                         cudaFuncAttributeMaxDynamicSharedMemorySize, SMEM_BYTES);

    float* qW;   cudaGetSymbolAddress((void**)&qW,   g_qW);
    float* Wt;   cudaGetSymbolAddress((void**)&Wt,   g_Wt);
    float* valT; cudaGetSymbolAddress((void**)&valT, g_valT);

    // Prep: W^T and values^T so every GEMM is NT (B consumed [N,K] row-major)
    transpose_kernel<<<dim3(32, 32, 1),  dim3(32, 8)>>>(W, Wt);
    transpose_kernel<<<dim3(32, 32, 16), dim3(32, 8)>>>(values, valT);

    // qW = query @ W : one 16384x1024x1024 NT GEMM (W batch-shared), 3-term
    gemm_fp16_kernel<false, 3><<<dim3(8, 128, 1), 128, SMEM_BYTES>>>(
        query, Wt, qW, nullptr, 0, 0, 0);

    // logits = qW @ keys^T + mask -> score (NT), 3-term (softmax amplifies logit error)
    gemm_fp16_kernel<true, 3><<<dim3(8, 8, 16), 128, SMEM_BYTES>>>(
        qW, keys, score, mask, 1048576, 1048576, 1048576);

    // softmax in place over last dim
    softmax_kernel<<<16384, 256>>>(score);

    // ctx = score @ values (NT on values^T), 2-term: full-A x f16-hi-B (~2e-4 rel)
    gemm_fp16_kernel<false, 2><<<dim3(8, 8, 16), 128, SMEM_BYTES>>>(
        score, valT, ctx, nullptr, 1048576, 1048576, 1048576);
}

// round 8
// speedup vs baseline: 1.1170x; 1.1170x over previous
#include <cuda_runtime.h>
#include <cuda_fp16.h>
#include <cstdint>

// Bilinear attention, B=16, T=D=1024:
//   qW = query @ W ; logits = qW @ keys^T + mask ; score = softmax(logits) ; ctx = score @ values
// GEMMs via mma.sync.m16n8k16 fp16, error-compensated split, fp32 accumulate.
// Producer-side split: raw f32 LDG -> split once -> half2 planes in SMEM;
// consumer fragments are single LDS.32 loads (zero ALU in MMA phase).
// All GEMMs NT (W, values transposed up front). 128 thr/CTA, warp tile 64x64,
// 2-slot plane ring, one barrier per 16-k chunk.
// TERMS: 3 = Ahi*Bhi+Ahi*Blo+Alo*Bhi (logit path, near-fp32)
//        1 = Ahi*Bhi (post-softmax GEMM; adds ~2^-11 quadrature error, within budget)

#define NDIM 1024

// Static scratch (allocation-guard safe)
__device__ float g_qW[16777216];    // 16384 x 1024
__device__ float g_Wt[1048576];     // W^T
__device__ float g_valT[16777216];  // values^T per batch

// ---- helpers -------------------------------------------------------------
static __device__ __forceinline__ uint32_t pack_h2(float e0, float e1) {
    uint32_t r;   // r.lo = f16(e0), r.hi = f16(e1)
    asm("cvt.rn.f16x2.f32 %0, %1, %2;" : "=r"(r) : "f"(e1), "f"(e0));
    return r;
}
static __device__ __forceinline__ void split_pair(float x, float y, uint32_t& h, uint32_t& l) {
    h = pack_h2(x, y);
    __half2 hh = *reinterpret_cast<__half2*>(&h);
    l = pack_h2(x - __low2float(hh), y - __high2float(hh));
}
static __device__ __forceinline__ void mma16(float* d, const uint32_t* a, const uint32_t* b) {
    asm volatile(
        "mma.sync.aligned.m16n8k16.row.col.f32.f16.f16.f32 "
        "{%0,%1,%2,%3}, {%4,%5,%6,%7}, {%8,%9}, {%0,%1,%2,%3};"
        : "+f"(d[0]), "+f"(d[1]), "+f"(d[2]), "+f"(d[3])
        : "r"(a[0]), "r"(a[1]), "r"(a[2]), "r"(a[3]), "r"(b[0]), "r"(b[1]));
}

// ---- SMEM plane layout ----------------------------------------------------
// Row = 16 halves data + 8 halves pad = 48 bytes (conflict-free frag LDS + STS).
// Planes per slot: A-hi, A-lo, B-hi, B-lo, each 128 rows x 48B = 6144 B.
#define ROWB 48
#define AH_OFF 0
#define AL_OFF 6144
#define BH_OFF 12288
#define BL_OFF 18432
#define SLOT_BYTES 24576
static constexpr int SMEM_BYTES = 2 * SLOT_BYTES;   // 49152

template<bool ADDMASK, int TERMS>
__global__ __launch_bounds__(128) void gemm_fp16_kernel(
    const float* __restrict__ A, const float* __restrict__ B,
    float* __restrict__ C, const float* __restrict__ mask,
    size_t sA, size_t sB, size_t sC)
{
    extern __shared__ __align__(16) char smem[];
    const int tid = threadIdx.x, wid = tid >> 5, lid = tid & 31;
    const int g = lid >> 2, tg = lid & 3;                  // mma group / thread-in-group
    const int wm = (wid >> 1) * 64, wn = (wid & 1) * 64;   // 2x2 warp grid, 64x64 tiles
    const int M0 = blockIdx.y * 128, N0 = blockIdx.x * 128;
    const size_t b = blockIdx.z;
    A += b * sA; B += b * sB; C += b * sC;
    const float* mp = ADDMASK ? (mask + b * 1024) : nullptr;

    // producer geometry: r = row-in-pass (0..31, +32 per pass), q = k-quarter
    const int r = tid >> 2, q = tid & 3;
    const float* Ag = A + (size_t)(M0 + r) * NDIM + 4 * q;
    const float* Bg = B + (size_t)(N0 + r) * NDIM + 4 * q;

    float acc[4][8][4];
    #pragma unroll
    for (int mi = 0; mi < 4; mi++)
        #pragma unroll
        for (int ni = 0; ni < 8; ni++)
            #pragma unroll
            for (int v = 0; v < 4; v++) acc[mi][ni][v] = 0.0f;

    float4 bufA[4], bufB[4];

    auto ldg = [&](int c) {
        const int k0 = c << 4;
        #pragma unroll
        for (int p = 0; p < 4; p++) {
            bufA[p] = *(const float4*)(Ag + (size_t)32 * p * NDIM + k0);
            bufB[p] = *(const float4*)(Bg + (size_t)32 * p * NDIM + k0);
        }
    };

    auto sts = [&](int slot) {
        char* base = smem + slot * SLOT_BYTES;
        #pragma unroll
        for (int p = 0; p < 4; p++) {
            const int ro = (r + 32 * p) * ROWB + q * 8;
            uint32_t h0, h1, l0, l1;
            if (TERMS >= 2) {
                split_pair(bufA[p].x, bufA[p].y, h0, l0);
                split_pair(bufA[p].z, bufA[p].w, h1, l1);
                *(uint2*)(base + AH_OFF + ro) = make_uint2(h0, h1);
                *(uint2*)(base + AL_OFF + ro) = make_uint2(l0, l1);
            } else {
                h0 = pack_h2(bufA[p].x, bufA[p].y);
                h1 = pack_h2(bufA[p].z, bufA[p].w);
                *(uint2*)(base + AH_OFF + ro) = make_uint2(h0, h1);
            }
            if (TERMS == 3) {
                split_pair(bufB[p].x, bufB[p].y, h0, l0);
                split_pair(bufB[p].z, bufB[p].w, h1, l1);
                *(uint2*)(base + BH_OFF + ro) = make_uint2(h0, h1);
                *(uint2*)(base + BL_OFF + ro) = make_uint2(l0, l1);
            } else {
                h0 = pack_h2(bufB[p].x, bufB[p].y);
                h1 = pack_h2(bufB[p].z, bufB[p].w);
                *(uint2*)(base + BH_OFF + ro) = make_uint2(h0, h1);
            }
        }
    };

    auto frag_mma = [&](int slot) {
        const char* base = smem + slot * SLOT_BYTES;
        // cache all B fragments (n reused over 4 mi)
        uint32_t bh[8][2], bl[8][2];
        #pragma unroll
        for (int ni = 0; ni < 8; ni++) {
            const int n0 = (wn + ni * 8 + g) * ROWB + tg * 4;
            bh[ni][0] = *(const uint32_t*)(base + BH_OFF + n0);
            bh[ni][1] = *(const uint32_t*)(base + BH_OFF + n0 + 16);
            if (TERMS == 3) {
                bl[ni][0] = *(const uint32_t*)(base + BL_OFF + n0);
                bl[ni][1] = *(const uint32_t*)(base + BL_OFF + n0 + 16);
            }
        }
        #pragma unroll
        for (int mi = 0; mi < 4; mi++) {
            const int r0 = (wm + mi * 16 + g) * ROWB + tg * 4;
            const int r1 = r0 + 8 * ROWB;
            uint32_t ah[4], al[4];
            ah[0] = *(const uint32_t*)(base + AH_OFF + r0);
            ah[1] = *(const uint32_t*)(base + AH_OFF + r1);
            ah[2] = *(const uint32_t*)(base + AH_OFF + r0 + 16);
            ah[3] = *(const uint32_t*)(base + AH_OFF + r1 + 16);
            if (TERMS >= 2) {
                al[0] = *(const uint32_t*)(base + AL_OFF + r0);
                al[1] = *(const uint32_t*)(base + AL_OFF + r1);
                al[2] = *(const uint32_t*)(base + AL_OFF + r0 + 16);
                al[3] = *(const uint32_t*)(base + AL_OFF + r1 + 16);
            }
            #pragma unroll
            for (int ni = 0; ni < 8; ni++) {
                mma16(acc[mi][ni], ah, bh[ni]);
                if (TERMS == 3) mma16(acc[mi][ni], ah, bl[ni]);
                if (TERMS >= 2) mma16(acc[mi][ni], al, bh[ni]);
            }
        }
    };

    // prologue: fill slot 0
    ldg(0);
    sts(0);
    __syncthreads();

    for (int c = 0; c < 64; c++) {
        if (c + 1 < 64) ldg(c + 1);       // in flight during MMA phase
        frag_mma(c & 1);
        if (c + 1 < 64) sts((c + 1) & 1); // slot was drained in iter c-1 (bar'ed)
        __syncthreads();
    }

    // epilogue: d0,d1 at (g, 2tg..2tg+1), d2,d3 at (g+8, ...)
    #pragma unroll
    for (int mi = 0; mi < 4; mi++) {
        #pragma unroll
        for (int ni = 0; ni < 8; ni++) {
            const int r0 = M0 + wm + mi * 16 + g;
            const int cc = N0 + wn + ni * 8 + 2 * tg;
            float2 v0 = make_float2(acc[mi][ni][0], acc[mi][ni][1]);
            float2 v1 = make_float2(acc[mi][ni][2], acc[mi][ni][3]);
            if (ADDMASK) {
                const float m0v = mp[cc], m1v = mp[cc + 1];
                v0.x += m0v; v0.y += m1v;
                v1.x += m0v; v1.y += m1v;
            }
            *(float2*)(C + (size_t)r0 * NDIM + cc)       = v0;
            *(float2*)(C + (size_t)(r0 + 8) * NDIM + cc) = v1;
        }
    }
}

// 1024x1024 f32 transpose (per blockIdx.z slice), block (32,8)
__global__ __launch_bounds__(256) void transpose_kernel(const float* __restrict__ src,
                                                        float* __restrict__ dst)
{
    __shared__ float t[32][33];
    const size_t b = blockIdx.z;
    src += b * 1048576ull; dst += b * 1048576ull;
    const int bx = blockIdx.x * 32, by = blockIdx.y * 32;
    const int x = threadIdx.x, y4 = threadIdx.y * 4;
    #pragma unroll
    for (int i = 0; i < 4; i++)
        t[y4 + i][x] = src[(size_t)(by + y4 + i) * 1024 + bx + x];
    __syncthreads();
    #pragma unroll
    for (int i = 0; i < 4; i++)
        dst[(size_t)(bx + y4 + i) * 1024 + by + x] = t[x][y4 + i];
}

// In-place row softmax, row length 1024
__global__ __launch_bounds__(256) void softmax_kernel(float* __restrict__ S)
{
    __shared__ float red[8];
    size_t row = blockIdx.x;
    float4* p = reinterpret_cast<float4*>(S + row * 1024);
    int t = threadIdx.x;

    float4 v = p[t];
    float m = fmaxf(fmaxf(v.x, v.y), fmaxf(v.z, v.w));
    #pragma unroll
    for (int o = 16; o; o >>= 1) m = fmaxf(m, __shfl_xor_sync(0xffffffffu, m, o));
    if ((t & 31) == 0) red[t >> 5] = m;
    __syncthreads();
    m = red[0];
    #pragma unroll
    for (int i = 1; i < 8; i++) m = fmaxf(m, red[i]);

    v.x = expf(v.x - m); v.y = expf(v.y - m);
    v.z = expf(v.z - m); v.w = expf(v.w - m);
    float s = v.x + v.y + v.z + v.w;
    #pragma unroll
    for (int o = 16; o; o >>= 1) s += __shfl_xor_sync(0xffffffffu, s, o);
    __syncthreads();
    if ((t & 31) == 0) red[t >> 5] = s;
    __syncthreads();
    s = red[0];
    #pragma unroll
    for (int i = 1; i < 8; i++) s += red[i];

    float inv = 1.0f / s;
    v.x *= inv; v.y *= inv; v.z *= inv; v.w *= inv;
    p[t] = v;
}

extern "C" void kernel_launch(void* const* d_in, const int* in_sizes, int n_in,
                              void* d_out, int out_size)
{
    (void)in_sizes; (void)n_in; (void)out_size;
    const float* query  = (const float*)d_in[0];   // [16,1024,1024]
    const float* keys   = (const float*)d_in[1];   // [16,1024,1024]
    const float* values = (const float*)d_in[2];   // [16,1024,1024]
    const float* W      = (const float*)d_in[3];   // [1024,1024]
    const float* mask   = (const float*)d_in[4];   // [16,1024]

    float* score = (float*)d_out;                        // [16,1024,1024]
    float* ctx   = score + (size_t)16 * 1024 * 1024;     // [16,1024,1024]

    cudaFuncSetAttribute(gemm_fp16_kernel<false, 3>,
                         cudaFuncAttributeMaxDynamicSharedMemorySize, SMEM_BYTES);
    cudaFuncSetAttribute(gemm_fp16_kernel<true, 3>,
                         cudaFuncAttributeMaxDynamicSharedMemorySize, SMEM_BYTES);
    cudaFuncSetAttribute(gemm_fp16_kernel<false, 1>,
                         cudaFuncAttributeMaxDynamicSharedMemorySize, SMEM_BYTES);

    float* qW;   cudaGetSymbolAddress((void**)&qW,   g_qW);
    float* Wt;   cudaGetSymbolAddress((void**)&Wt,   g_Wt);
    float* valT; cudaGetSymbolAddress((void**)&valT, g_valT);

    // Prep: W^T and values^T so every GEMM is NT (B consumed [N,K] row-major)
    transpose_kernel<<<dim3(32, 32, 1),  dim3(32, 8)>>>(W, Wt);
    transpose_kernel<<<dim3(32, 32, 16), dim3(32, 8)>>>(values, valT);

    // qW = query @ W : one 16384x1024x1024 NT GEMM (W batch-shared), 3-term
    gemm_fp16_kernel<false, 3><<<dim3(8, 128, 1), 128, SMEM_BYTES>>>(
        query, Wt, qW, nullptr, 0, 0, 0);

    // logits = qW @ keys^T + mask -> score (NT), 3-term (softmax amplifies logit error)
    gemm_fp16_kernel<true, 3><<<dim3(8, 8, 16), 128, SMEM_BYTES>>>(
        qW, keys, score, mask, 1048576, 1048576, 1048576);

    // softmax in place over last dim
    softmax_kernel<<<16384, 256>>>(score);

    // ctx = score @ values (NT on values^T), 1-term pure fp16 (~5e-4 rel total)
    gemm_fp16_kernel<false, 1><<<dim3(8, 8, 16), 128, SMEM_BYTES>>>(
        score, valT, ctx, nullptr, 1048576, 1048576, 1048576);
}